// round 1
// baseline (speedup 1.0000x reference)
#include <cuda_runtime.h>

#define S_LEN 2048
#define BATCH 2
#define DM 512
#define HD 64
#define NH 8
#define M_TOT (BATCH * S_LEN)   // 4096

// Scratch (allocation-free rule: __device__ globals)
__device__ float g_q[M_TOT * DM];
__device__ float g_k[M_TOT * DM];
__device__ float g_v[M_TOT * DM];
__device__ float g_attn[M_TOT * DM];

// ---------------------------------------------------------------------------
// SGEMM: C[M,512] = A[M,512] @ B[512,512]
// 128x128 block tile, BK=16, 256 threads, 8x8 per thread.
// blockIdx.z selects (W,C) pair so QKV is one fused launch.
// ---------------------------------------------------------------------------
__global__ void __launch_bounds__(256, 2) sgemm_kernel(
    const float* __restrict__ A,
    const float* __restrict__ W0, const float* __restrict__ W1, const float* __restrict__ W2,
    float* __restrict__ C0, float* __restrict__ C1, float* __restrict__ C2)
{
    constexpr int BK = 16;
    constexpr int N = 512, K = 512;
    __shared__ float As[BK][132];   // transposed A tile [k][m], padded
    __shared__ float Bs[BK][128];   // B tile [k][n]

    const float* __restrict__ B = (blockIdx.z == 0) ? W0 : ((blockIdx.z == 1) ? W1 : W2);
    float* __restrict__ C = (blockIdx.z == 0) ? C0 : ((blockIdx.z == 1) ? C1 : C2);

    const int tid = threadIdx.x;
    const int tm = tid >> 4;          // 0..15
    const int tn = tid & 15;          // 0..15
    const int row0 = blockIdx.x * 128;
    const int col0 = blockIdx.y * 128;

    float acc[8][8] = {};

    for (int k0 = 0; k0 < K; k0 += BK) {
#pragma unroll
        for (int i = 0; i < 2; i++) {
            int l = tid + i * 256;
            // A: 128 rows x 16 k -> transpose into As
            int r = l >> 2, kv = l & 3;
            float4 va = *reinterpret_cast<const float4*>(&A[(size_t)(row0 + r) * K + k0 + kv * 4]);
            As[kv * 4 + 0][r] = va.x;
            As[kv * 4 + 1][r] = va.y;
            As[kv * 4 + 2][r] = va.z;
            As[kv * 4 + 3][r] = va.w;
            // B: 16 rows x 128 n, natural layout
            int kr = l >> 5, nv = l & 31;
            *reinterpret_cast<float4*>(&Bs[kr][nv * 4]) =
                *reinterpret_cast<const float4*>(&B[(size_t)(k0 + kr) * N + col0 + nv * 4]);
        }
        __syncthreads();
#pragma unroll
        for (int kk = 0; kk < BK; kk++) {
            float a[8], b[8];
            *reinterpret_cast<float4*>(&a[0]) = *reinterpret_cast<const float4*>(&As[kk][tm * 8]);
            *reinterpret_cast<float4*>(&a[4]) = *reinterpret_cast<const float4*>(&As[kk][tm * 8 + 4]);
            *reinterpret_cast<float4*>(&b[0]) = *reinterpret_cast<const float4*>(&Bs[kk][tn * 8]);
            *reinterpret_cast<float4*>(&b[4]) = *reinterpret_cast<const float4*>(&Bs[kk][tn * 8 + 4]);
#pragma unroll
            for (int i = 0; i < 8; i++)
#pragma unroll
                for (int j = 0; j < 8; j++)
                    acc[i][j] = fmaf(a[i], b[j], acc[i][j]);
        }
        __syncthreads();
    }

#pragma unroll
    for (int i = 0; i < 8; i++) {
        size_t r = (size_t)(row0 + tm * 8 + i);
#pragma unroll
        for (int j = 0; j < 8; j += 4) {
            float4 v = make_float4(acc[i][j], acc[i][j + 1], acc[i][j + 2], acc[i][j + 3]);
            *reinterpret_cast<float4*>(&C[r * N + col0 + tn * 8 + j]) = v;
        }
    }
}

// ---------------------------------------------------------------------------
// Flash attention (non-causal, full). Grid: (S/64, NH, BATCH), 256 threads.
// Br=Bc=64, hd=64. 16x16 thread layout, 4x4 fragments.
// Smem: Qt[k][r], U (Kt[k][c] reused as swizzled P[r][c]), Vs[c][d] = 48KB.
// ---------------------------------------------------------------------------
__global__ void __launch_bounds__(256) attn_kernel()
{
    __shared__ float Qt[64][64];  // transposed Q tile, pre-scaled by 1/8
    __shared__ float U [64][64];  // Kt, then P (ty-parity XOR-16 column swizzle)
    __shared__ float Vs[64][64];  // V tile, natural [key][d]

    const int tid = threadIdx.x;
    const int ty = tid >> 4;      // 0..15 : q-row group
    const int tx = tid & 15;      // 0..15 : key/d group
    const int b = blockIdx.z;
    const int h = blockIdx.y;
    const int q0 = blockIdx.x * 64;

    const size_t rowbase = (size_t)b * S_LEN;
    const int hoff = h * HD;
    const int swz = (ty & 1) << 4;

    // Load Q tile transposed & scaled. r-fast mapping: smem stores conflict-free.
#pragma unroll
    for (int i = 0; i < 4; i++) {
        int l = tid + i * 256;
        int r = l & 63, kv = l >> 6;
        float4 v = *reinterpret_cast<const float4*>(
            &g_q[(rowbase + q0 + r) * DM + hoff + kv * 4]);
        Qt[kv * 4 + 0][r] = v.x * 0.125f;
        Qt[kv * 4 + 1][r] = v.y * 0.125f;
        Qt[kv * 4 + 2][r] = v.z * 0.125f;
        Qt[kv * 4 + 3][r] = v.w * 0.125f;
    }

    float accO[4][4] = {};
    float m_i[4], l_i[4];
#pragma unroll
    for (int i = 0; i < 4; i++) { m_i[i] = -1e30f; l_i[i] = 0.0f; }

    for (int j0 = 0; j0 < S_LEN; j0 += 64) {
        __syncthreads();   // previous tile's P/V readers done (also covers Q store)
#pragma unroll
        for (int i = 0; i < 4; i++) {
            int l = tid + i * 256;
            // K transposed, r-fast (conflict-free transpose stores; L2-resident reads)
            int c = l & 63, kv = l >> 6;
            float4 vk = *reinterpret_cast<const float4*>(
                &g_k[(rowbase + j0 + c) * DM + hoff + kv * 4]);
            U[kv * 4 + 0][c] = vk.x;
            U[kv * 4 + 1][c] = vk.y;
            U[kv * 4 + 2][c] = vk.z;
            U[kv * 4 + 3][c] = vk.w;
            // V natural, kv-fast (fully coalesced)
            int c2 = l >> 4, kv2 = l & 15;
            *reinterpret_cast<float4*>(&Vs[c2][kv2 * 4]) =
                *reinterpret_cast<const float4*>(
                    &g_v[(rowbase + j0 + c2) * DM + hoff + kv2 * 4]);
        }
        __syncthreads();

        // S = (Q*scale) @ K^T : 4x4 fragment per thread
        float s[4][4] = {};
#pragma unroll
        for (int kk = 0; kk < 64; kk++) {
            float a[4], bb[4];
            *reinterpret_cast<float4*>(a)  = *reinterpret_cast<const float4*>(&Qt[kk][ty * 4]);
            *reinterpret_cast<float4*>(bb) = *reinterpret_cast<const float4*>(&U[kk][tx * 4]);
#pragma unroll
            for (int i = 0; i < 4; i++)
#pragma unroll
                for (int j = 0; j < 4; j++)
                    s[i][j] = fmaf(a[i], bb[j], s[i][j]);
        }

        // Online softmax (rows owned by the 16 tx-lanes of each ty group)
#pragma unroll
        for (int i = 0; i < 4; i++) {
            float mx = fmaxf(fmaxf(s[i][0], s[i][1]), fmaxf(s[i][2], s[i][3]));
#pragma unroll
            for (int off = 1; off < 16; off <<= 1)
                mx = fmaxf(mx, __shfl_xor_sync(0xffffffffu, mx, off));
            float mnew = fmaxf(m_i[i], mx);
            float corr = __expf(m_i[i] - mnew);
            m_i[i] = mnew;
            float rs = 0.0f;
#pragma unroll
            for (int j = 0; j < 4; j++) {
                s[i][j] = __expf(s[i][j] - mnew);
                rs += s[i][j];
            }
#pragma unroll
            for (int off = 1; off < 16; off <<= 1)
                rs += __shfl_xor_sync(0xffffffffu, rs, off);
            l_i[i] = l_i[i] * corr + rs;
#pragma unroll
            for (int j = 0; j < 4; j++)
                accO[i][j] *= corr;
        }

        __syncthreads();   // all threads done reading Kt from U
        // Store P into U with ty-parity column swizzle (conflict-free reads later)
#pragma unroll
        for (int i = 0; i < 4; i++) {
            float4 v = make_float4(s[i][0], s[i][1], s[i][2], s[i][3]);
            *reinterpret_cast<float4*>(&U[ty * 4 + i][(tx * 4) ^ swz]) = v;
        }
        __syncthreads();

        // O += P @ V
#pragma unroll
        for (int kk = 0; kk < 64; kk++) {
            float a[4], bb[4];
            const int ck = kk ^ swz;
            a[0] = U[ty * 4 + 0][ck];
            a[1] = U[ty * 4 + 1][ck];
            a[2] = U[ty * 4 + 2][ck];
            a[3] = U[ty * 4 + 3][ck];
            *reinterpret_cast<float4*>(bb) = *reinterpret_cast<const float4*>(&Vs[kk][tx * 4]);
#pragma unroll
            for (int i = 0; i < 4; i++)
#pragma unroll
                for (int j = 0; j < 4; j++)
                    accO[i][j] = fmaf(a[i], bb[j], accO[i][j]);
        }
    }

    // Finalize: divide by row sums, write out
#pragma unroll
    for (int i = 0; i < 4; i++) {
        float inv = 1.0f / l_i[i];
        size_t r = rowbase + q0 + ty * 4 + i;
        float4 v = make_float4(accO[i][0] * inv, accO[i][1] * inv,
                               accO[i][2] * inv, accO[i][3] * inv);
        *reinterpret_cast<float4*>(&g_attn[r * DM + hoff + tx * 4]) = v;
    }
}

// ---------------------------------------------------------------------------
extern "C" void kernel_launch(void* const* d_in, const int* in_sizes, int n_in,
                              void* d_out, int out_size)
{
    const float* h  = (const float*)d_in[0];
    const float* Wq = (const float*)d_in[1];
    const float* Wk = (const float*)d_in[2];
    const float* Wv = (const float*)d_in[3];
    const float* Wo = (const float*)d_in[4];
    float* out = (float*)d_out;

    float *q, *k, *v, *attn;
    cudaGetSymbolAddress((void**)&q, g_q);
    cudaGetSymbolAddress((void**)&k, g_k);
    cudaGetSymbolAddress((void**)&v, g_v);
    cudaGetSymbolAddress((void**)&attn, g_attn);

    // Fused QKV projections
    dim3 g1(M_TOT / 128, 512 / 128, 3);
    sgemm_kernel<<<g1, 256>>>(h, Wq, Wk, Wv, q, k, v);

    // Flash attention
    dim3 g2(S_LEN / 64, NH, BATCH);
    attn_kernel<<<g2, 256>>>();

    // Output projection
    dim3 g3(M_TOT / 128, 512 / 128, 1);
    sgemm_kernel<<<g3, 256>>>(attn, Wo, Wo, Wo, out, out, out);
}

// round 2
// speedup vs baseline: 3.4005x; 3.4005x over previous
#include <cuda_runtime.h>

#define S_LEN 2048
#define BATCH 2
#define DM 512
#define HD 64
#define NH 8
#define M_TOT (BATCH * S_LEN)   // 4096

// Scratch (allocation-free rule: __device__ globals)
__device__ float g_q[M_TOT * DM];
__device__ float g_k[M_TOT * DM];
__device__ float g_v[M_TOT * DM];
__device__ float g_attn[M_TOT * DM];

// ---------------------------------------------------------------------------
// tf32 helpers
// ---------------------------------------------------------------------------
__device__ __forceinline__ unsigned f2tf(float f) {
    unsigned u;
    asm("cvt.rna.tf32.f32 %0, %1;" : "=r"(u) : "f"(f));
    return u;
}

// D = A(16x8,row) * B(8x8,col) + D, fp32 accum
__device__ __forceinline__ void mma8(float* c, const unsigned* a, const unsigned* b) {
    asm volatile(
        "mma.sync.aligned.m16n8k8.row.col.f32.tf32.tf32.f32 "
        "{%0,%1,%2,%3}, {%4,%5,%6,%7}, {%8,%9}, {%0,%1,%2,%3};"
        : "+f"(c[0]), "+f"(c[1]), "+f"(c[2]), "+f"(c[3])
        : "r"(a[0]), "r"(a[1]), "r"(a[2]), "r"(a[3]), "r"(b[0]), "r"(b[1]));
}

// ---------------------------------------------------------------------------
// tf32 GEMM: C[M,512] = A[M,512] @ B[512,512]
// 128x128 tile, BK=32, 256 threads (8 warps, 2x4 warp grid, 64x32 warp tile).
// As[m][k] stride 36 (≡4 mod 32: A-frag scalar LDS conflict-free)
// Bs[k][n] stride 136 (≡8 mod 32: B-frag scalar LDS conflict-free)
// ---------------------------------------------------------------------------
#define GST_A 36
#define GST_B 136

__global__ void __launch_bounds__(256, 2) gemm_tf32(
    const float* __restrict__ A,
    const float* __restrict__ W0, const float* __restrict__ W1, const float* __restrict__ W2,
    float* __restrict__ C0, float* __restrict__ C1, float* __restrict__ C2)
{
    __shared__ unsigned As[128 * GST_A];
    __shared__ unsigned Bs[32 * GST_B];

    const float* __restrict__ B = (blockIdx.z == 0) ? W0 : ((blockIdx.z == 1) ? W1 : W2);
    float* __restrict__ C = (blockIdx.z == 0) ? C0 : ((blockIdx.z == 1) ? C1 : C2);

    const int tid = threadIdx.x;
    const int warp = tid >> 5, lane = tid & 31;
    const int gid = lane >> 2, tig = lane & 3;
    const int wm = warp >> 2, wn = warp & 3;     // 2 x 4 warps
    const int row0 = blockIdx.x * 128, col0 = blockIdx.y * 128;

    float acc[4][4][4] = {};   // [mt][nt][c0..c3]

    for (int k0 = 0; k0 < 512; k0 += 32) {
        __syncthreads();
        // A tile: 128 x 32, natural [m][k]
#pragma unroll
        for (int i = 0; i < 4; i++) {
            int idx = tid + i * 256;
            int r = idx >> 3, f4 = idx & 7;
            float4 v = *(const float4*)&A[(size_t)(row0 + r) * 512 + k0 + f4 * 4];
            unsigned* dst = &As[r * GST_A + f4 * 4];
            dst[0] = f2tf(v.x); dst[1] = f2tf(v.y); dst[2] = f2tf(v.z); dst[3] = f2tf(v.w);
        }
        // B tile: 32 x 128, natural [k][n]
#pragma unroll
        for (int i = 0; i < 4; i++) {
            int idx = tid + i * 256;
            int kr = idx >> 5, f4 = idx & 31;
            float4 v = *(const float4*)&B[(size_t)(k0 + kr) * 512 + col0 + f4 * 4];
            unsigned* dst = &Bs[kr * GST_B + f4 * 4];
            dst[0] = f2tf(v.x); dst[1] = f2tf(v.y); dst[2] = f2tf(v.z); dst[3] = f2tf(v.w);
        }
        __syncthreads();

#pragma unroll
        for (int ks = 0; ks < 4; ks++) {
            unsigned a[4][4];
#pragma unroll
            for (int mt = 0; mt < 4; mt++) {
                const unsigned* ap = &As[(wm * 64 + mt * 16 + gid) * GST_A + ks * 8 + tig];
                a[mt][0] = ap[0];
                a[mt][1] = ap[8 * GST_A];
                a[mt][2] = ap[4];
                a[mt][3] = ap[8 * GST_A + 4];
            }
#pragma unroll
            for (int nt = 0; nt < 4; nt++) {
                unsigned bf[2];
                const unsigned* bp = &Bs[(ks * 8 + tig) * GST_B + wn * 32 + nt * 8 + gid];
                bf[0] = bp[0];
                bf[1] = bp[4 * GST_B];
#pragma unroll
                for (int mt = 0; mt < 4; mt++)
                    mma8(acc[mt][nt], a[mt], bf);
            }
        }
    }

#pragma unroll
    for (int mt = 0; mt < 4; mt++) {
        int r = row0 + wm * 64 + mt * 16 + gid;
#pragma unroll
        for (int nt = 0; nt < 4; nt++) {
            int c = col0 + wn * 32 + nt * 8 + tig * 2;
            *(float2*)&C[(size_t)r * 512 + c]       = make_float2(acc[mt][nt][0], acc[mt][nt][1]);
            *(float2*)&C[(size_t)(r + 8) * 512 + c] = make_float2(acc[mt][nt][2], acc[mt][nt][3]);
        }
    }
}

// ---------------------------------------------------------------------------
// tf32 flash attention. Grid (S/128, NH, BATCH), 256 threads = 8 warps.
// Each warp owns a 16-row q slab (m16); per 64-key tile: QK = 8x8 mma,
// online softmax (quad shuffles), P->smem (within-warp only), PV = 8x8 mma.
// Smem (tf32 bits, dynamic): Qs[128][68], Ks[64][68], Vs[64][72], Ps[128][68]
//   A-side stride 68 (≡4 mod 32), B-natural stride 72 (≡8 mod 32): all
//   fragment LDS conflict-free.
// ---------------------------------------------------------------------------
#define AST 68
#define BST 72
#define QS_OFF 0
#define KS_OFF (128 * AST)            // 8704
#define VS_OFF (KS_OFF + 64 * AST)    // 13056
#define PS_OFF (VS_OFF + 64 * BST)    // 17664
#define SMEM_U32 (PS_OFF + 128 * AST) // 26368 u32 = 105472 B

__global__ void __launch_bounds__(256, 2) attn_tf32()
{
    extern __shared__ unsigned smu[];
    unsigned* Qs = smu + QS_OFF;
    unsigned* Ks = smu + KS_OFF;
    unsigned* Vs = smu + VS_OFF;
    unsigned* Ps = smu + PS_OFF;

    const int tid = threadIdx.x;
    const int warp = tid >> 5, lane = tid & 31;
    const int gid = lane >> 2, tig = lane & 3;
    const int b = blockIdx.z, h = blockIdx.y;
    const int q0 = blockIdx.x * 128;
    const size_t rowbase = (size_t)b * S_LEN;
    const int hoff = h * HD;

    // Stage Q (pre-scaled by 1/sqrt(64)=0.125) : 128 x 64
#pragma unroll
    for (int i = 0; i < 8; i++) {
        int idx = tid + i * 256;
        int r = idx >> 4, f4 = idx & 15;
        float4 v = *(const float4*)&g_q[(rowbase + q0 + r) * DM + hoff + f4 * 4];
        unsigned* dst = &Qs[r * AST + f4 * 4];
        dst[0] = f2tf(v.x * 0.125f); dst[1] = f2tf(v.y * 0.125f);
        dst[2] = f2tf(v.z * 0.125f); dst[3] = f2tf(v.w * 0.125f);
    }

    float o[8][4] = {};
    float mr[2] = {-1e30f, -1e30f};
    float lr[2] = {0.0f, 0.0f};

    const int rbase = warp * 16 + gid;   // this thread's row (and rbase+8)

    for (int j0 = 0; j0 < S_LEN; j0 += 64) {
        __syncthreads();   // prev tile's PV reads of Vs done (first iter: Q staged)
        // K tile [key][d] natural, V tile [key][d] natural — both coalesced
#pragma unroll
        for (int i = 0; i < 4; i++) {
            int idx = tid + i * 256;
            int r = idx >> 4, f4 = idx & 15;
            const size_t g = (rowbase + j0 + r) * DM + hoff + f4 * 4;
            float4 vk = *(const float4*)&g_k[g];
            unsigned* d1 = &Ks[r * AST + f4 * 4];
            d1[0] = f2tf(vk.x); d1[1] = f2tf(vk.y); d1[2] = f2tf(vk.z); d1[3] = f2tf(vk.w);
            float4 vv = *(const float4*)&g_v[g];
            unsigned* d2 = &Vs[r * BST + f4 * 4];
            d2[0] = f2tf(vv.x); d2[1] = f2tf(vv.y); d2[2] = f2tf(vv.z); d2[3] = f2tf(vv.w);
        }
        __syncthreads();

        // ---- S = Q @ K^T  (warp: 16 x 64) ----
        float s[8][4] = {};
#pragma unroll
        for (int ks = 0; ks < 8; ks++) {
            unsigned a[4];
            const unsigned* ap = &Qs[rbase * AST + ks * 8 + tig];
            a[0] = ap[0]; a[1] = ap[8 * AST]; a[2] = ap[4]; a[3] = ap[8 * AST + 4];
#pragma unroll
            for (int j = 0; j < 8; j++) {
                unsigned bf[2];
                const unsigned* bp = &Ks[(j * 8 + gid) * AST + ks * 8 + tig];
                bf[0] = bp[0]; bf[1] = bp[4];
                mma8(s[j], a, bf);
            }
        }

        // ---- online softmax (rows rbase, rbase+8; quad reduction) ----
#pragma unroll
        for (int rs2 = 0; rs2 < 2; rs2++) {
            float mx = -1e30f;
#pragma unroll
            for (int j = 0; j < 8; j++)
                mx = fmaxf(mx, fmaxf(s[j][rs2 * 2], s[j][rs2 * 2 + 1]));
            mx = fmaxf(mx, __shfl_xor_sync(0xffffffffu, mx, 1));
            mx = fmaxf(mx, __shfl_xor_sync(0xffffffffu, mx, 2));
            float mnew = fmaxf(mr[rs2], mx);
            float corr = __expf(mr[rs2] - mnew);
            mr[rs2] = mnew;
            float rsum = 0.0f;
#pragma unroll
            for (int j = 0; j < 8; j++) {
                float e0 = __expf(s[j][rs2 * 2]     - mnew);
                float e1 = __expf(s[j][rs2 * 2 + 1] - mnew);
                s[j][rs2 * 2] = e0; s[j][rs2 * 2 + 1] = e1;
                rsum += e0 + e1;
            }
            rsum += __shfl_xor_sync(0xffffffffu, rsum, 1);
            rsum += __shfl_xor_sync(0xffffffffu, rsum, 2);
            lr[rs2] = lr[rs2] * corr + rsum;
#pragma unroll
            for (int j = 0; j < 8; j++) {
                o[j][rs2 * 2] *= corr; o[j][rs2 * 2 + 1] *= corr;
            }
        }

        // ---- P -> smem (within-warp exchange only) ----
        __syncwarp();
#pragma unroll
        for (int j = 0; j < 8; j++) {
            *(uint2*)&Ps[rbase * AST + j * 8 + tig * 2] =
                make_uint2(f2tf(s[j][0]), f2tf(s[j][1]));
            *(uint2*)&Ps[(rbase + 8) * AST + j * 8 + tig * 2] =
                make_uint2(f2tf(s[j][2]), f2tf(s[j][3]));
        }
        __syncwarp();

        // ---- O += P @ V  (warp: 16 x 64, k = 64 keys) ----
#pragma unroll
        for (int ks = 0; ks < 8; ks++) {
            unsigned a[4];
            const unsigned* ap = &Ps[rbase * AST + ks * 8 + tig];
            a[0] = ap[0]; a[1] = ap[8 * AST]; a[2] = ap[4]; a[3] = ap[8 * AST + 4];
#pragma unroll
            for (int j = 0; j < 8; j++) {
                unsigned bf[2];
                const unsigned* bp = &Vs[(ks * 8 + tig) * BST + j * 8 + gid];
                bf[0] = bp[0]; bf[1] = bp[4 * BST];
                mma8(o[j], a, bf);
            }
        }
    }

    // ---- finalize ----
    float inv0 = 1.0f / lr[0], inv1 = 1.0f / lr[1];
    const size_t r0 = rowbase + q0 + rbase;
#pragma unroll
    for (int j = 0; j < 8; j++) {
        int c = hoff + j * 8 + tig * 2;
        *(float2*)&g_attn[r0 * DM + c]       = make_float2(o[j][0] * inv0, o[j][1] * inv0);
        *(float2*)&g_attn[(r0 + 8) * DM + c] = make_float2(o[j][2] * inv1, o[j][3] * inv1);
    }
}

// ---------------------------------------------------------------------------
extern "C" void kernel_launch(void* const* d_in, const int* in_sizes, int n_in,
                              void* d_out, int out_size)
{
    const float* h  = (const float*)d_in[0];
    const float* Wq = (const float*)d_in[1];
    const float* Wk = (const float*)d_in[2];
    const float* Wv = (const float*)d_in[3];
    const float* Wo = (const float*)d_in[4];
    float* out = (float*)d_out;

    float *q, *k, *v, *attn;
    cudaGetSymbolAddress((void**)&q, g_q);
    cudaGetSymbolAddress((void**)&k, g_k);
    cudaGetSymbolAddress((void**)&v, g_v);
    cudaGetSymbolAddress((void**)&attn, g_attn);

    cudaFuncSetAttribute(attn_tf32, cudaFuncAttributeMaxDynamicSharedMemorySize,
                         SMEM_U32 * 4);

    // Fused QKV projections (tf32)
    dim3 g1(M_TOT / 128, 512 / 128, 3);
    gemm_tf32<<<g1, 256>>>(h, Wq, Wk, Wv, q, k, v);

    // Flash attention (tf32)
    dim3 g2(S_LEN / 128, NH, BATCH);
    attn_tf32<<<g2, 256, SMEM_U32 * 4>>>();

    // Output projection (tf32)
    dim3 g3(M_TOT / 128, 512 / 128, 1);
    gemm_tf32<<<g3, 256>>>(attn, Wo, Wo, Wo, out, out, out);
}

// round 4
// speedup vs baseline: 3.4859x; 1.0251x over previous
#include <cuda_runtime.h>
#include <cstdint>

#define S_LEN 2048
#define BATCH 2
#define DM 512
#define HD 64
#define NH 8
#define M_TOT (BATCH * S_LEN)   // 4096

// Scratch (allocation-free rule: __device__ globals)
__device__ float g_q[M_TOT * DM];
__device__ float g_k[M_TOT * DM];
__device__ float g_v[M_TOT * DM];
__device__ float g_attn[M_TOT * DM];

// ---------------------------------------------------------------------------
// tf32 helpers
// ---------------------------------------------------------------------------
__device__ __forceinline__ unsigned f2tf(float f) {
    unsigned u;
    asm("cvt.rna.tf32.f32 %0, %1;" : "=r"(u) : "f"(f));
    return u;
}

// D = A(16x8,row) * B(8x8,col) + D, fp32 accum
__device__ __forceinline__ void mma8(float* c, const unsigned* a, const unsigned* b) {
    asm volatile(
        "mma.sync.aligned.m16n8k8.row.col.f32.tf32.tf32.f32 "
        "{%0,%1,%2,%3}, {%4,%5,%6,%7}, {%8,%9}, {%0,%1,%2,%3};"
        : "+f"(c[0]), "+f"(c[1]), "+f"(c[2]), "+f"(c[3])
        : "r"(a[0]), "r"(a[1]), "r"(a[2]), "r"(a[3]), "r"(b[0]), "r"(b[1]));
}

// ---------------------------------------------------------------------------
// tf32 GEMM (UNCHANGED from R2 — known correct): C[M,512] = A[M,512] @ B[512,512]
// ---------------------------------------------------------------------------
#define GST_A 36
#define GST_B 136

__global__ void __launch_bounds__(256, 2) gemm_tf32(
    const float* __restrict__ A,
    const float* __restrict__ W0, const float* __restrict__ W1, const float* __restrict__ W2,
    float* __restrict__ C0, float* __restrict__ C1, float* __restrict__ C2)
{
    __shared__ unsigned As[128 * GST_A];
    __shared__ unsigned Bs[32 * GST_B];

    const float* __restrict__ B = (blockIdx.z == 0) ? W0 : ((blockIdx.z == 1) ? W1 : W2);
    float* __restrict__ C = (blockIdx.z == 0) ? C0 : ((blockIdx.z == 1) ? C1 : C2);

    const int tid = threadIdx.x;
    const int warp = tid >> 5, lane = tid & 31;
    const int gid = lane >> 2, tig = lane & 3;
    const int wm = warp >> 2, wn = warp & 3;
    const int row0 = blockIdx.x * 128, col0 = blockIdx.y * 128;

    float acc[4][4][4] = {};

    for (int k0 = 0; k0 < 512; k0 += 32) {
        __syncthreads();
#pragma unroll
        for (int i = 0; i < 4; i++) {
            int idx = tid + i * 256;
            int r = idx >> 3, f4 = idx & 7;
            float4 v = *(const float4*)&A[(size_t)(row0 + r) * 512 + k0 + f4 * 4];
            unsigned* dst = &As[r * GST_A + f4 * 4];
            dst[0] = f2tf(v.x); dst[1] = f2tf(v.y); dst[2] = f2tf(v.z); dst[3] = f2tf(v.w);
        }
#pragma unroll
        for (int i = 0; i < 4; i++) {
            int idx = tid + i * 256;
            int kr = idx >> 5, f4 = idx & 31;
            float4 v = *(const float4*)&B[(size_t)(k0 + kr) * 512 + col0 + f4 * 4];
            unsigned* dst = &Bs[kr * GST_B + f4 * 4];
            dst[0] = f2tf(v.x); dst[1] = f2tf(v.y); dst[2] = f2tf(v.z); dst[3] = f2tf(v.w);
        }
        __syncthreads();

#pragma unroll
        for (int ks = 0; ks < 4; ks++) {
            unsigned a[4][4];
#pragma unroll
            for (int mt = 0; mt < 4; mt++) {
                const unsigned* ap = &As[(wm * 64 + mt * 16 + gid) * GST_A + ks * 8 + tig];
                a[mt][0] = ap[0];
                a[mt][1] = ap[8 * GST_A];
                a[mt][2] = ap[4];
                a[mt][3] = ap[8 * GST_A + 4];
            }
#pragma unroll
            for (int nt = 0; nt < 4; nt++) {
                unsigned bf[2];
                const unsigned* bp = &Bs[(ks * 8 + tig) * GST_B + wn * 32 + nt * 8 + gid];
                bf[0] = bp[0];
                bf[1] = bp[4 * GST_B];
#pragma unroll
                for (int mt = 0; mt < 4; mt++)
                    mma8(acc[mt][nt], a[mt], bf);
            }
        }
    }

#pragma unroll
    for (int mt = 0; mt < 4; mt++) {
        int r = row0 + wm * 64 + mt * 16 + gid;
#pragma unroll
        for (int nt = 0; nt < 4; nt++) {
            int c = col0 + wn * 32 + nt * 8 + tig * 2;
            *(float2*)&C[(size_t)r * 512 + c]       = make_float2(acc[mt][nt][0], acc[mt][nt][1]);
            *(float2*)&C[(size_t)(r + 8) * 512 + c] = make_float2(acc[mt][nt][2], acc[mt][nt][3]);
        }
    }
}

// ---------------------------------------------------------------------------
// tf32 flash attention v2: Q-frags in registers, fragment-packed K/V (LDS.64
// per MMA), double-buffered K/V tiles (1 sync per tile).
//
// Fragment pack (both K and V): block b = j*8 + ks (j = n-dim octet, ks =
// k-dim octet), 64 blocks, stride 66 u32. Reader: uint2 at b*66 + lane*2.
//   K (QK^T):  n-dim = key, k-dim = d.   element(key,d): b=(key>>3)*8+(d>>3),
//              lane=4*(key&7)+(d&3) ... wait — see stager comments below.
//   V (P@V):   n-dim = d,  k-dim = key.
// Layout per buffer: Kf[4224] ++ Vf[4224] u32. Ps (P exchange) unchanged AST=68.
// ---------------------------------------------------------------------------
#define KVST 66
#define BUF_U32 8448                    // Kf 4224 + Vf 4224
#define PS_OFF2 (2 * BUF_U32)           // 16896
#define AST 68
#define SMEM_ATT_U32 (PS_OFF2 + 128 * AST)   // 25600 u32 = 102400 B

__device__ __forceinline__ void stage_kv(unsigned* sm, int buf, size_t gbase) {
    unsigned* Kf = sm + buf * BUF_U32;
    unsigned* Vf = Kf + 4224;
    const int tid = threadIdx.x;

    // ---- K: QK b-frag (ks,j,lane): bf0 = K[j*8+gid][ks*8+tig], bf1 = +4 in d.
    // element (key r, dim d): b = (r>>3)*8 + (d>>3); lane = 4*(r&7)+(d&3);
    // slot = (d&7)>>2.  Stager: r = idx>>4, f4 = idx&15 (d = 4*f4+e).
#pragma unroll
    for (int i = 0; i < 4; i++) {
        int idx = tid + i * 256;
        int r = idx >> 4, f4 = idx & 15;
        float4 v = *(const float4*)&g_k[gbase + (size_t)r * DM + f4 * 4];
        int b = (r >> 3) * 8 + (f4 >> 1);
        unsigned* dst = &Kf[b * KVST + ((r & 7) * 4) * 2 + (f4 & 1)];
        dst[0] = f2tf(v.x);   // e=0..3: lane += e -> word += 2e
        dst[2] = f2tf(v.y);
        dst[4] = f2tf(v.z);
        dst[6] = f2tf(v.w);
    }

    // ---- V: PV b-frag (ks,j,lane): bf0 = V[ks*8+tig][j*8+gid], bf1 = +4 in key.
    // element (key r, dim d): b = (d>>3)*8 + (r>>3); lane = 4*(d&7)+(r&3);
    // slot = (r&7)>>2.  Stager: r = tid>>2, f4 = (tid&3)+4*i (d = 4*f4+e).
    {
        int r = tid >> 2;
        const float* vrow = &g_v[gbase + (size_t)r * DM];
        int lanelo = (r & 3);
        int slot = (r & 7) >> 2;
        int bks = (r >> 3);
#pragma unroll
        for (int i = 0; i < 4; i++) {
            int f4 = (tid & 3) + 4 * i;
            float4 v = *(const float4*)&vrow[f4 * 4];
            int b = (f4 >> 1) * 8 + bks;
            unsigned* dst = &Vf[b * KVST + (16 * (f4 & 1) + lanelo) * 2 + slot];
            dst[0]  = f2tf(v.x);   // e: lane += 4e -> word += 8e
            dst[8]  = f2tf(v.y);
            dst[16] = f2tf(v.z);
            dst[24] = f2tf(v.w);
        }
    }
}

__global__ void __launch_bounds__(256, 2) attn_tf32()
{
    extern __shared__ unsigned smu[];
    unsigned* Ps = smu + PS_OFF2;

    const int tid = threadIdx.x;
    const int warp = tid >> 5, lane = tid & 31;
    const int gid = lane >> 2, tig = lane & 3;
    const int b = blockIdx.z, h = blockIdx.y;
    const int q0 = blockIdx.x * 128;
    const size_t rowbase = (size_t)b * S_LEN;
    const int hoff = h * HD;
    const int rbase = warp * 16 + gid;
    const int lane2 = lane * 2;

    // ---- Q fragments: registers, loaded once (pre-scaled by 1/8) ----
    unsigned Qf[8][4];
    {
        const size_t qrow = (rowbase + q0 + rbase) * DM + hoff;
#pragma unroll
        for (int ks = 0; ks < 8; ks++) {
            int c = ks * 8 + tig;
            Qf[ks][0] = f2tf(0.125f * g_q[qrow + c]);
            Qf[ks][1] = f2tf(0.125f * g_q[qrow + 8 * DM + c]);
            Qf[ks][2] = f2tf(0.125f * g_q[qrow + c + 4]);
            Qf[ks][3] = f2tf(0.125f * g_q[qrow + 8 * DM + c + 4]);
        }
    }

    float o[8][4] = {};
    float mr[2] = {-1e30f, -1e30f};
    float lr[2] = {0.0f, 0.0f};

    // prologue: stage tile 0
    stage_kv(smu, 0, (rowbase + 0) * DM + hoff);
    __syncthreads();

    for (int t = 0; t < 32; t++) {
        // stage next tile into the other buffer (overlaps compute)
        if (t + 1 < 32)
            stage_kv(smu, (t + 1) & 1, (rowbase + (size_t)(t + 1) * 64) * DM + hoff);

        const unsigned* Kf = smu + (t & 1) * BUF_U32;
        const unsigned* Vf = Kf + 4224;

        // ---- S = Q @ K^T : 64 MMAs, one LDS.64 each ----
        float s[8][4] = {};
#pragma unroll
        for (int ks = 0; ks < 8; ks++) {
#pragma unroll
            for (int j = 0; j < 8; j++) {
                uint2 bf = *(const uint2*)&Kf[(j * 8 + ks) * KVST + lane2];
                mma8(s[j], Qf[ks], (const unsigned*)&bf);
            }
        }

        // ---- online softmax (rows rbase, rbase+8; quad reduction) ----
#pragma unroll
        for (int rs2 = 0; rs2 < 2; rs2++) {
            float mx = -1e30f;
#pragma unroll
            for (int j = 0; j < 8; j++)
                mx = fmaxf(mx, fmaxf(s[j][rs2 * 2], s[j][rs2 * 2 + 1]));
            mx = fmaxf(mx, __shfl_xor_sync(0xffffffffu, mx, 1));
            mx = fmaxf(mx, __shfl_xor_sync(0xffffffffu, mx, 2));
            float mnew = fmaxf(mr[rs2], mx);
            float corr = __expf(mr[rs2] - mnew);
            mr[rs2] = mnew;
            float rsum = 0.0f;
#pragma unroll
            for (int j = 0; j < 8; j++) {
                float e0 = __expf(s[j][rs2 * 2]     - mnew);
                float e1 = __expf(s[j][rs2 * 2 + 1] - mnew);
                s[j][rs2 * 2] = e0; s[j][rs2 * 2 + 1] = e1;
                rsum += e0 + e1;
            }
            rsum += __shfl_xor_sync(0xffffffffu, rsum, 1);
            rsum += __shfl_xor_sync(0xffffffffu, rsum, 2);
            lr[rs2] = lr[rs2] * corr + rsum;
#pragma unroll
            for (int j = 0; j < 8; j++) {
                o[j][rs2 * 2] *= corr; o[j][rs2 * 2 + 1] *= corr;
            }
        }

        // ---- P -> smem (within-warp exchange only) ----
        __syncwarp();
#pragma unroll
        for (int j = 0; j < 8; j++) {
            *(uint2*)&Ps[rbase * AST + j * 8 + tig * 2] =
                make_uint2(f2tf(s[j][0]), f2tf(s[j][1]));
            *(uint2*)&Ps[(rbase + 8) * AST + j * 8 + tig * 2] =
                make_uint2(f2tf(s[j][2]), f2tf(s[j][3]));
        }
        __syncwarp();

        // ---- O += P @ V : 64 MMAs, LDS.64 for V frags ----
#pragma unroll
        for (int ks = 0; ks < 8; ks++) {
            unsigned a[4];
            const unsigned* ap = &Ps[rbase * AST + ks * 8 + tig];
            a[0] = ap[0]; a[1] = ap[8 * AST]; a[2] = ap[4]; a[3] = ap[8 * AST + 4];
#pragma unroll
            for (int j = 0; j < 8; j++) {
                uint2 bf = *(const uint2*)&Vf[(j * 8 + ks) * KVST + lane2];
                mma8(o[j], a, (const unsigned*)&bf);
            }
        }

        __syncthreads();   // staging of t+1 visible; compute of t done everywhere
    }

    // ---- finalize ----
    float inv0 = 1.0f / lr[0], inv1 = 1.0f / lr[1];
    const size_t r0 = rowbase + q0 + rbase;
#pragma unroll
    for (int j = 0; j < 8; j++) {
        int c = hoff + j * 8 + tig * 2;
        *(float2*)&g_attn[r0 * DM + c]       = make_float2(o[j][0] * inv0, o[j][1] * inv0);
        *(float2*)&g_attn[(r0 + 8) * DM + c] = make_float2(o[j][2] * inv1, o[j][3] * inv1);
    }
}

// ---------------------------------------------------------------------------
extern "C" void kernel_launch(void* const* d_in, const int* in_sizes, int n_in,
                              void* d_out, int out_size)
{
    const float* h  = (const float*)d_in[0];
    const float* Wq = (const float*)d_in[1];
    const float* Wk = (const float*)d_in[2];
    const float* Wv = (const float*)d_in[3];
    const float* Wo = (const float*)d_in[4];
    float* out = (float*)d_out;

    float *q, *k, *v, *attn;
    cudaGetSymbolAddress((void**)&q, g_q);
    cudaGetSymbolAddress((void**)&k, g_k);
    cudaGetSymbolAddress((void**)&v, g_v);
    cudaGetSymbolAddress((void**)&attn, g_attn);

    cudaFuncSetAttribute(attn_tf32, cudaFuncAttributeMaxDynamicSharedMemorySize,
                         SMEM_ATT_U32 * 4);

    // Fused QKV projections (tf32)
    dim3 g1(M_TOT / 128, 512 / 128, 3);
    gemm_tf32<<<g1, 256>>>(h, Wq, Wk, Wv, q, k, v);

    // Flash attention (tf32, packed fragments, double-buffered)
    dim3 g2(S_LEN / 128, NH, BATCH);
    attn_tf32<<<g2, 256, SMEM_ATT_U32 * 4>>>();

    // Output projection (tf32)
    dim3 g3(M_TOT / 128, 512 / 128, 1);
    gemm_tf32<<<g3, 256>>>(attn, Wo, Wo, Wo, out, out, out);
}